// round 6
// baseline (speedup 1.0000x reference)
#include <cuda_runtime.h>
#include <cuda_bf16.h>
#include <math.h>

static constexpr int kNL = 4;        // layers
static constexpr int kNB = 64;       // batch
static constexpr int kNH = 1024;     // hidden
static constexpr int kNT = 128;      // time steps
static constexpr int kNG = 4096;     // gate columns (4*kNH)
static constexpr int kSteps = 512;   // kNT*kNL layer-steps
static constexpr int kTiles = 32;    // N-tiles per layer-step
static constexpr int kAStride = 24;  // bf16 elems per A smem row (48B)
static constexpr int kWStride = 136; // bf16 elems per W smem row (272B)

static constexpr size_t kWElems = (size_t)kNL * kNH * kNG;
static constexpr size_t kXElems = (size_t)kNT * kNB * kNH;
static constexpr size_t kHElems = (size_t)kNL * kNB * kNH;

// ---------------- persistent device state (sanctioned scratch) ----------------
// alignas(128): cp.async requires 16B-aligned global srcs; all computed offsets
// below are 16B multiples relative to these bases.
__device__ alignas(128) __nv_bfloat16 g_Wi_hi[kWElems];
__device__ alignas(128) __nv_bfloat16 g_Wi_lo[kWElems];
__device__ alignas(128) __nv_bfloat16 g_Wh_hi[kWElems];
__device__ alignas(128) __nv_bfloat16 g_Wh_lo[kWElems];
__device__ alignas(128) __nv_bfloat16 g_x_hi[kXElems];
__device__ alignas(128) __nv_bfloat16 g_x_lo[kXElems];
__device__ alignas(128) __nv_bfloat16 g_h_hi[2][kNL][kNB][kNH];  // parity double buffer
__device__ alignas(128) __nv_bfloat16 g_h_lo[2][kNL][kNB][kNH];
__device__ alignas(128) float g_cell[kNL][kNB][kNH];
__device__ alignas(128) float g_part[4][kNB][kNG];   // per-K-chunk GEMM partials
__device__ int g_arrive[kSteps][kTiles];             // arrival counters (wait-free)

// ---------------- helpers ----------------
__device__ __forceinline__ float sigmoid_f(float x) { return 1.0f / (1.0f + expf(-x)); }

__device__ __forceinline__ unsigned smem_addr_u32(const void* p) {
    return (unsigned)__cvta_generic_to_shared(p);
}
__device__ __forceinline__ void copy_async16(unsigned dst, const void* src) {
    asm volatile("cp.async.cg.shared.global [%0], [%1], 16;" :: "r"(dst), "l"(src));
}
__device__ __forceinline__ void copy_commit() { asm volatile("cp.async.commit_group;"); }
__device__ __forceinline__ void copy_wait1() { asm volatile("cp.async.wait_group 1;"); }
__device__ __forceinline__ void copy_wait0() { asm volatile("cp.async.wait_group 0;"); }

__device__ __forceinline__ void ldmatrix_a(unsigned* r, unsigned addr) {
    asm volatile("ldmatrix.sync.aligned.m8n8.x4.shared.b16 {%0,%1,%2,%3}, [%4];"
        : "=r"(r[0]), "=r"(r[1]), "=r"(r[2]), "=r"(r[3]) : "r"(addr));
}
__device__ __forceinline__ void ldmatrix_bt(unsigned* r, unsigned addr) {
    asm volatile("ldmatrix.sync.aligned.m8n8.x4.trans.shared.b16 {%0,%1,%2,%3}, [%4];"
        : "=r"(r[0]), "=r"(r[1]), "=r"(r[2]), "=r"(r[3]) : "r"(addr));
}
__device__ __forceinline__ void mma_bf16(float* acc, const unsigned* afrag, const unsigned* bfrag) {
    asm volatile("mma.sync.aligned.m16n8k16.row.col.f32.bf16.bf16.f32 "
        "{%0,%1,%2,%3},{%4,%5,%6,%7},{%8,%9},{%0,%1,%2,%3};"
        : "+f"(acc[0]), "+f"(acc[1]), "+f"(acc[2]), "+f"(acc[3])
        : "r"(afrag[0]), "r"(afrag[1]), "r"(afrag[2]), "r"(afrag[3]),
          "r"(bfrag[0]), "r"(bfrag[1]));
}

// Issue one pipeline stage of cp.async loads (A: 1 vec16/thread, W: 2 vec16/thread).
__device__ __forceinline__ void load_stage(
    unsigned smem_a_base, unsigned smem_w_base, int buf, int kb,
    const __nv_bfloat16* act_hi, const __nv_bfloat16* act_lo,
    const __nv_bfloat16* wgt_hi, const __nv_bfloat16* wgt_lo,
    int tid, int unit0)
{
    int a_half = tid >> 7;
    int a_row  = (tid & 127) >> 1;
    int a_vec  = tid & 1;
    const __nv_bfloat16* a_src =
        (a_half ? act_lo : act_hi) + (size_t)a_row * kNH + kb + a_vec * 8;
    unsigned a_dst = smem_a_base +
        (unsigned)((((buf * 2 + a_half) * 64 + a_row) * kAStride + a_vec * 8) * 2);
    copy_async16(a_dst, a_src);

    #pragma unroll
    for (int j = 0; j < 2; ++j) {
        int wid2   = tid + j * 256;
        int w_half = wid2 >> 8;
        int rem    = wid2 & 255;
        int krow   = rem >> 4;
        int seg    = rem & 15;
        int gate   = seg >> 2;
        int vec    = seg & 3;
        const __nv_bfloat16* w_src = (w_half ? wgt_lo : wgt_hi)
            + (size_t)(kb + krow) * kNG + gate * kNH + unit0 + vec * 8;
        unsigned w_dst = smem_w_base +
            (unsigned)((((buf * 2 + w_half) * 16 + krow) * kWStride + gate * 32 + vec * 8) * 2);
        copy_async16(w_dst, w_src);
    }
}

// ---------------- prep: split-bf16 conversion + state/counter reset ----------------
__global__ void prep_k(const float* __restrict__ Wi, const float* __restrict__ Wh,
                       const float* __restrict__ x) {
    size_t tid  = (size_t)blockIdx.x * blockDim.x + threadIdx.x;
    size_t nthr = (size_t)gridDim.x * blockDim.x;
    for (size_t i = tid; i < kWElems; i += nthr) {
        float wv = Wi[i];
        __nv_bfloat16 top = __float2bfloat16_rn(wv);
        g_Wi_hi[i] = top;
        g_Wi_lo[i] = __float2bfloat16_rn(wv - __bfloat162float(top));
        wv  = Wh[i];
        top = __float2bfloat16_rn(wv);
        g_Wh_hi[i] = top;
        g_Wh_lo[i] = __float2bfloat16_rn(wv - __bfloat162float(top));
    }
    for (size_t i = tid; i < kXElems; i += nthr) {
        float xv = x[i];
        __nv_bfloat16 top = __float2bfloat16_rn(xv);
        g_x_hi[i] = top;
        g_x_lo[i] = __float2bfloat16_rn(xv - __bfloat162float(top));
    }
    __nv_bfloat16 zero_b = __float2bfloat16_rn(0.0f);
    __nv_bfloat16* hp = &g_h_hi[0][0][0][0];
    __nv_bfloat16* lp = &g_h_lo[0][0][0][0];
    for (size_t i = tid; i < 2 * kHElems; i += nthr) { hp[i] = zero_b; lp[i] = zero_b; }
    float* cp = &g_cell[0][0][0];
    for (size_t i = tid; i < kHElems; i += nthr) cp[i] = 0.0f;
    int* ap = &g_arrive[0][0];
    for (size_t i = tid; i < (size_t)kSteps * kTiles; i += nthr) ap[i] = 0;
}

// ---------------- one layer-step: GEMM + fused cell (wait-free) ----------------
// 128 blocks x 256 threads. Block b: tile = b>>2 (32 units x 4 gates = 128 gate cols),
// chunk = b&3 (K range of 512 within the 2048-wide [x ; h] reduction).
// Cross-step ordering: stream order. Cross-chunk reduction: atomic arrival
// counter; the 4th arriver applies the LSTM cell. No spin loops anywhere.
__global__ __launch_bounds__(256, 1) void step_k(
    const float* __restrict__ bias_all,  // [kNL][kNG]
    float* __restrict__ out_buf,         // [3][kNB][kNH]
    int step_e)
{
    __shared__ alignas(128) __nv_bfloat16 smem_a[2 * 2 * 64 * kAStride];
    __shared__ alignas(128) __nv_bfloat16 smem_w[2 * 2 * 16 * kWStride];
    __shared__ int smem_flag;

    const int tid   = threadIdx.x;
    const int lane  = tid & 31;
    const int warp  = tid >> 5;
    const int ncol0 = warp * 16;
    const int tile  = blockIdx.x >> 2;
    const int chunk = blockIdx.x & 3;
    const int unit0 = tile * 32;
    const int lrow  = lane & 15;
    const int lcol  = lane >> 4;

    const int tstep = step_e >> 2;
    const int layer = step_e & 3;
    const int par_cur  = tstep & 1;
    const int par_prev = par_cur ^ 1;

    const unsigned smem_a_base = smem_addr_u32(smem_a);
    const unsigned smem_w_base = smem_addr_u32(smem_w);

    // Operand selection
    const __nv_bfloat16 *act_hi, *act_lo, *wgt_hi, *wgt_lo;
    int kbase;
    if (chunk < 2) {
        wgt_hi = g_Wi_hi + (size_t)layer * kNH * kNG;
        wgt_lo = g_Wi_lo + (size_t)layer * kNH * kNG;
        if (layer == 0) {
            act_hi = g_x_hi + (size_t)tstep * kNB * kNH;
            act_lo = g_x_lo + (size_t)tstep * kNB * kNH;
        } else {
            act_hi = &g_h_hi[par_cur][layer - 1][0][0];
            act_lo = &g_h_lo[par_cur][layer - 1][0][0];
        }
        kbase = chunk * 512;
    } else {
        wgt_hi = g_Wh_hi + (size_t)layer * kNH * kNG;
        wgt_lo = g_Wh_lo + (size_t)layer * kNH * kNG;
        act_hi = &g_h_hi[par_prev][layer][0][0];   // h(t-1); zeros at t=0 via prep
        act_lo = &g_h_lo[par_prev][layer][0][0];
        kbase = (chunk - 2) * 512;
    }

    float acc[4][2][4];
    #pragma unroll
    for (int mt = 0; mt < 4; ++mt)
        #pragma unroll
        for (int nt = 0; nt < 2; ++nt)
            #pragma unroll
            for (int r = 0; r < 4; ++r) acc[mt][nt][r] = 0.0f;

    load_stage(smem_a_base, smem_w_base, 0, kbase,
               act_hi, act_lo, wgt_hi, wgt_lo, tid, unit0);
    copy_commit();

    #pragma unroll 1
    for (int iter = 0; iter < 32; ++iter) {
        if (iter < 31) {
            load_stage(smem_a_base, smem_w_base, (iter + 1) & 1, kbase + (iter + 1) * 16,
                       act_hi, act_lo, wgt_hi, wgt_lo, tid, unit0);
            copy_commit();
            copy_wait1();
        } else {
            copy_wait0();
        }
        __syncthreads();

        const int buf = iter & 1;
        unsigned addr_a_hi = smem_a_base +
            (unsigned)((((buf * 2 + 0) * 64 + lrow) * kAStride + lcol * 8) * 2);
        unsigned addr_a_lo = smem_a_base +
            (unsigned)((((buf * 2 + 1) * 64 + lrow) * kAStride + lcol * 8) * 2);
        unsigned addr_w_hi = smem_w_base +
            (unsigned)((((buf * 2 + 0) * 16 + lrow) * kWStride + ncol0 + lcol * 8) * 2);
        unsigned addr_w_lo = smem_w_base +
            (unsigned)((((buf * 2 + 1) * 16 + lrow) * kWStride + ncol0 + lcol * 8) * 2);

        unsigned frag_a_hi[4][4], frag_a_lo[4][4], frag_b_hi[4], frag_b_lo[4];
        #pragma unroll
        for (int mt = 0; mt < 4; ++mt) {
            ldmatrix_a(frag_a_hi[mt], addr_a_hi + mt * 16 * kAStride * 2);
            ldmatrix_a(frag_a_lo[mt], addr_a_lo + mt * 16 * kAStride * 2);
        }
        ldmatrix_bt(frag_b_hi, addr_w_hi);
        ldmatrix_bt(frag_b_lo, addr_w_lo);

        #pragma unroll
        for (int mt = 0; mt < 4; ++mt) {
            #pragma unroll
            for (int nt = 0; nt < 2; ++nt) {
                mma_bf16(acc[mt][nt], frag_a_lo[mt], &frag_b_hi[nt * 2]);
                mma_bf16(acc[mt][nt], frag_a_hi[mt], &frag_b_lo[nt * 2]);
                mma_bf16(acc[mt][nt], frag_a_hi[mt], &frag_b_hi[nt * 2]);
            }
        }
        __syncthreads();
    }

    // ---- store partials ----
    {
        float* part = &g_part[chunk][0][0];
        #pragma unroll
        for (int mt = 0; mt < 4; ++mt) {
            #pragma unroll
            for (int nt = 0; nt < 2; ++nt) {
                int row  = mt * 16 + (lane >> 2);
                int col  = ncol0 + nt * 8 + 2 * (lane & 3);
                int gate = col >> 5;
                int gcol = gate * kNH + unit0 + (col & 31);
                float2 v0 = make_float2(acc[mt][nt][0], acc[mt][nt][1]);
                float2 v1 = make_float2(acc[mt][nt][2], acc[mt][nt][3]);
                *(float2*)&part[(size_t)row * kNG + gcol]       = v0;
                *(float2*)&part[(size_t)(row + 8) * kNG + gcol] = v1;
            }
        }
    }

    __threadfence();
    __syncthreads();
    if (tid == 0) smem_flag = atomicAdd(&g_arrive[step_e][tile], 1);
    __syncthreads();

    if (smem_flag != 3) return;   // first 3 arrivers exit — wait-free by construction

    // 4th arriver: fused LSTM cell for this tile (2048 elements).
    __threadfence();
    const float* bias_l = bias_all + (size_t)layer * kNG;
    #pragma unroll 1
    for (int rep = 0; rep < 8; ++rep) {
        int idx  = rep * 256 + tid;     // 0..2047
        int uoff = idx & 31;
        int brow = idx >> 5;
        int unit = unit0 + uoff;
        float gate_i = 0.0f, gate_f = 0.0f, gate_g = 0.0f, gate_o = 0.0f;
        #pragma unroll
        for (int ch = 0; ch < 4; ++ch) {
            const float* pp = &g_part[ch][brow][0];
            gate_i += __ldcg(&pp[unit]);
            gate_f += __ldcg(&pp[kNH + unit]);
            gate_g += __ldcg(&pp[2 * kNH + unit]);
            gate_o += __ldcg(&pp[3 * kNH + unit]);
        }
        gate_i += bias_l[unit];
        gate_f += bias_l[kNH + unit];
        gate_g += bias_l[2 * kNH + unit];
        gate_o += bias_l[3 * kNH + unit];
        float cell_old = g_cell[layer][brow][unit];
        float act_i = sigmoid_f(gate_i);
        float act_f = sigmoid_f(gate_f);
        float act_o = sigmoid_f(gate_o);
        float cell_new = act_f * cell_old + act_i * tanhf(gate_g);
        float hid_new  = act_o * tanhf(cell_new);
        g_cell[layer][brow][unit] = cell_new;
        __nv_bfloat16 hid_top = __float2bfloat16_rn(hid_new);
        g_h_hi[par_cur][layer][brow][unit] = hid_top;
        g_h_lo[par_cur][layer][brow][unit] =
            __float2bfloat16_rn(hid_new - __bfloat162float(hid_top));
        if (step_e == kSteps - 1) {
            out_buf[(size_t)brow * kNH + unit]                         = hid_new;
            out_buf[(size_t)kNB * kNH + (size_t)brow * kNH + unit]     = hid_new;
            out_buf[(size_t)2 * kNB * kNH + (size_t)brow * kNH + unit] = cell_new;
        }
    }
}

extern "C" void kernel_launch(void* const* d_in, const int* in_sizes, int n_in,
                              void* d_out, int out_size) {
    const float* inp  = (const float*)d_in[0];  // [128,64,1024]
    const float* Wi   = (const float*)d_in[1];  // [4,1024,4096]
    const float* Wh   = (const float*)d_in[2];  // [4,1024,4096]
    const float* bias = (const float*)d_in[3];  // [4,4096]
    float* out = (float*)d_out;                 // [3,64,1024]

    prep_k<<<1024, 256>>>(Wi, Wh, inp);
    for (int e = 0; e < kSteps; ++e) {
        step_k<<<128, 256>>>(bias, out, e);
    }
}

// round 7
// speedup vs baseline: 1.2840x; 1.2840x over previous
#include <cuda_runtime.h>
#include <cuda_bf16.h>
#include <math.h>

static constexpr int kNL = 4;
static constexpr int kNB = 64;
static constexpr int kNH = 1024;
static constexpr int kNT = 128;
static constexpr int kNG = 4096;
static constexpr int kSteps = 512;    // kNT*kNL (arrival-counter indexing)
static constexpr int kTiles = 32;     // N-tiles per scan step
static constexpr int kAStride = 24;   // bf16 elems per A smem row (48B)
static constexpr int kWStride = 136;  // bf16 elems per W smem row (272B)

static constexpr size_t kWElems = (size_t)kNL * kNH * kNG;
static constexpr size_t kXElems = (size_t)kNT * kNB * kNH;
static constexpr size_t kHistElems = (size_t)(kNT + 1) * kNB * kNH;
static constexpr size_t kGinElems = (size_t)kNT * kNB * kNG;

// ---------------- persistent device state (sanctioned scratch) ----------------
__device__ alignas(128) __nv_bfloat16 g_Wi_hi[kWElems];
__device__ alignas(128) __nv_bfloat16 g_Wi_lo[kWElems];
__device__ alignas(128) __nv_bfloat16 g_Wh_hi[kWElems];
__device__ alignas(128) __nv_bfloat16 g_Wh_lo[kWElems];
__device__ alignas(128) __nv_bfloat16 g_x_hi[kXElems];
__device__ alignas(128) __nv_bfloat16 g_x_lo[kXElems];
__device__ alignas(128) __nv_bfloat16 g_hist_hi[kHistElems]; // hist[0]=zeros, hist[t+1]=h(t)
__device__ alignas(128) __nv_bfloat16 g_hist_lo[kHistElems];
__device__ alignas(128) float g_gin[kGinElems];              // x-side gates, fp32
__device__ alignas(128) float g_cell[kNB][kNH];              // per-layer c (t==0 skips read)
__device__ alignas(128) float g_part[4][kNB][kNG];           // per-K-chunk partials
__device__ int g_arrive[kSteps][kTiles];

// ---------------- helpers ----------------
__device__ __forceinline__ float sigmoid_f(float x) { return 1.0f / (1.0f + expf(-x)); }

__device__ __forceinline__ unsigned smem_addr_u32(const void* p) {
    return (unsigned)__cvta_generic_to_shared(p);
}
__device__ __forceinline__ void copy_async16(unsigned dst, const void* src) {
    asm volatile("cp.async.cg.shared.global [%0], [%1], 16;" :: "r"(dst), "l"(src));
}
__device__ __forceinline__ void copy_commit() { asm volatile("cp.async.commit_group;"); }
__device__ __forceinline__ void copy_wait1() { asm volatile("cp.async.wait_group 1;"); }
__device__ __forceinline__ void copy_wait2() { asm volatile("cp.async.wait_group 2;"); }

__device__ __forceinline__ void ldmatrix_a(unsigned* r, unsigned addr) {
    asm volatile("ldmatrix.sync.aligned.m8n8.x4.shared.b16 {%0,%1,%2,%3}, [%4];"
        : "=r"(r[0]), "=r"(r[1]), "=r"(r[2]), "=r"(r[3]) : "r"(addr));
}
__device__ __forceinline__ void ldmatrix_bt(unsigned* r, unsigned addr) {
    asm volatile("ldmatrix.sync.aligned.m8n8.x4.trans.shared.b16 {%0,%1,%2,%3}, [%4];"
        : "=r"(r[0]), "=r"(r[1]), "=r"(r[2]), "=r"(r[3]) : "r"(addr));
}
__device__ __forceinline__ void mma_bf16(float* acc, const unsigned* afrag, const unsigned* bfrag) {
    asm volatile("mma.sync.aligned.m16n8k16.row.col.f32.bf16.bf16.f32 "
        "{%0,%1,%2,%3},{%4,%5,%6,%7},{%8,%9},{%0,%1,%2,%3};"
        : "+f"(acc[0]), "+f"(acc[1]), "+f"(acc[2]), "+f"(acc[3])
        : "r"(afrag[0]), "r"(afrag[1]), "r"(afrag[2]), "r"(afrag[3]),
          "r"(bfrag[0]), "r"(bfrag[1]));
}

// ---------------- prep: split-bf16 conversion + reset ----------------
__global__ void prep_k(const float* __restrict__ Wi, const float* __restrict__ Wh,
                       const float* __restrict__ x) {
    size_t tid  = (size_t)blockIdx.x * blockDim.x + threadIdx.x;
    size_t nthr = (size_t)gridDim.x * blockDim.x;
    for (size_t i = tid; i < kWElems; i += nthr) {
        float wv = Wi[i];
        __nv_bfloat16 top = __float2bfloat16_rn(wv);
        g_Wi_hi[i] = top;
        g_Wi_lo[i] = __float2bfloat16_rn(wv - __bfloat162float(top));
        wv  = Wh[i];
        top = __float2bfloat16_rn(wv);
        g_Wh_hi[i] = top;
        g_Wh_lo[i] = __float2bfloat16_rn(wv - __bfloat162float(top));
    }
    for (size_t i = tid; i < kXElems; i += nthr) {
        float xv = x[i];
        __nv_bfloat16 top = __float2bfloat16_rn(xv);
        g_x_hi[i] = top;
        g_x_lo[i] = __float2bfloat16_rn(xv - __bfloat162float(top));
    }
    __nv_bfloat16 zero_b = __float2bfloat16_rn(0.0f);
    for (size_t i = tid; i < (size_t)kNB * kNH; i += nthr) {
        g_hist_hi[i] = zero_b;   // hist[0] = h(-1) = 0
        g_hist_lo[i] = zero_b;
    }
    int* ap = &g_arrive[0][0];
    for (size_t i = tid; i < (size_t)kSteps * kTiles; i += nthr) ap[i] = 0;
}

// ---------------- big input GEMM: g_gin = A @ Wi[layer], fp32 ----------------
// A = x (layer 0) or h history of the previous layer: [8192, 1024].
// Grid (32, 64): blockIdx.x = ntile (128 cols), blockIdx.y = mtile (128 rows).
// 256 threads = 8 warps in 2(M)x4(N); warp tile 64x32. 2-stage cp.async pipeline.
__device__ __forceinline__ void gemm_load_stage(
    unsigned sa_base, unsigned sw_base, int stage, int kb,
    const __nv_bfloat16* a_hi, const __nv_bfloat16* a_lo,
    const __nv_bfloat16* w_hi, const __nv_bfloat16* w_lo,
    int tid, int row0, int col0)
{
    #pragma unroll
    for (int j = 0; j < 2; ++j) {
        int id   = tid + j * 256;
        int half = id >> 8;
        int rem  = id & 255;
        int arow = rem >> 1;
        int avec = rem & 1;
        const __nv_bfloat16* src =
            (half ? a_lo : a_hi) + (size_t)(row0 + arow) * kNH + kb + avec * 8;
        unsigned dst = sa_base +
            (unsigned)((((stage * 2 + half) * 128 + arow) * kAStride + avec * 8) * 2);
        copy_async16(dst, src);
    }
    #pragma unroll
    for (int j = 0; j < 2; ++j) {
        int id   = tid + j * 256;
        int half = id >> 8;
        int rem  = id & 255;
        int krow = rem >> 4;
        int seg  = rem & 15;
        const __nv_bfloat16* src =
            (half ? w_lo : w_hi) + (size_t)(kb + krow) * kNG + col0 + seg * 8;
        unsigned dst = sw_base +
            (unsigned)((((stage * 2 + half) * 16 + krow) * kWStride + seg * 8) * 2);
        copy_async16(dst, src);
    }
}

__global__ __launch_bounds__(256, 1) void gemm_in_k(int layer) {
    __shared__ alignas(128) __nv_bfloat16 smem_a[2 * 2 * 128 * kAStride];
    __shared__ alignas(128) __nv_bfloat16 smem_w[2 * 2 * 16 * kWStride];

    const int tid   = threadIdx.x;
    const int lane  = tid & 31;
    const int warp  = tid >> 5;
    const int mwarp = warp >> 2;          // 0..1 (64 rows each)
    const int nwarp = warp & 3;           // 0..3 (32 cols each)
    const int lrow  = lane & 15;
    const int lcol  = lane >> 4;
    const int row0  = blockIdx.y * 128;
    const int col0  = blockIdx.x * 128;

    const __nv_bfloat16 *a_hi, *a_lo;
    if (layer == 0) { a_hi = g_x_hi; a_lo = g_x_lo; }
    else            { a_hi = g_hist_hi + (size_t)kNB * kNH; a_lo = g_hist_lo + (size_t)kNB * kNH; }
    const __nv_bfloat16* w_hi = g_Wi_hi + (size_t)layer * kNH * kNG;
    const __nv_bfloat16* w_lo = g_Wi_lo + (size_t)layer * kNH * kNG;

    const unsigned sa_base = smem_addr_u32(smem_a);
    const unsigned sw_base = smem_addr_u32(smem_w);

    float acc[4][4][4];
    #pragma unroll
    for (int mt = 0; mt < 4; ++mt)
        #pragma unroll
        for (int n8 = 0; n8 < 4; ++n8)
            #pragma unroll
            for (int r = 0; r < 4; ++r) acc[mt][n8][r] = 0.0f;

    gemm_load_stage(sa_base, sw_base, 0, 0,   a_hi, a_lo, w_hi, w_lo, tid, row0, col0);
    copy_commit();
    gemm_load_stage(sa_base, sw_base, 1, 16,  a_hi, a_lo, w_hi, w_lo, tid, row0, col0);
    copy_commit();

    #pragma unroll 1
    for (int iter = 0; iter < 64; ++iter) {
        copy_wait1();            // oldest of the (always) 2 outstanding groups done
        __syncthreads();

        const int buf = iter & 1;
        unsigned a_hi_b = sa_base + (unsigned)(((buf * 2 + 0) * 128) * kAStride * 2);
        unsigned a_lo_b = sa_base + (unsigned)(((buf * 2 + 1) * 128) * kAStride * 2);
        unsigned w_hi_b = sw_base + (unsigned)(((buf * 2 + 0) * 16) * kWStride * 2);
        unsigned w_lo_b = sw_base + (unsigned)(((buf * 2 + 1) * 16) * kWStride * 2);

        unsigned fa_hi[4][4], fa_lo[4][4], fb_hi[2][4], fb_lo[2][4];
        #pragma unroll
        for (int mt = 0; mt < 4; ++mt) {
            int row = mwarp * 64 + mt * 16 + lrow;
            ldmatrix_a(fa_hi[mt], a_hi_b + (unsigned)((row * kAStride + lcol * 8) * 2));
            ldmatrix_a(fa_lo[mt], a_lo_b + (unsigned)((row * kAStride + lcol * 8) * 2));
        }
        #pragma unroll
        for (int bn = 0; bn < 2; ++bn) {
            int ncol = nwarp * 32 + bn * 16 + lcol * 8;
            ldmatrix_bt(fb_hi[bn], w_hi_b + (unsigned)((lrow * kWStride + ncol) * 2));
            ldmatrix_bt(fb_lo[bn], w_lo_b + (unsigned)((lrow * kWStride + ncol) * 2));
        }
        #pragma unroll
        for (int mt = 0; mt < 4; ++mt) {
            #pragma unroll
            for (int n8 = 0; n8 < 4; ++n8) {
                const unsigned* bh = &fb_hi[n8 >> 1][(n8 & 1) * 2];
                const unsigned* bl = &fb_lo[n8 >> 1][(n8 & 1) * 2];
                mma_bf16(acc[mt][n8], fa_lo[mt], bh);
                mma_bf16(acc[mt][n8], fa_hi[mt], bl);
                mma_bf16(acc[mt][n8], fa_hi[mt], bh);
            }
        }
        __syncthreads();
        if (iter + 2 < 64)
            gemm_load_stage(sa_base, sw_base, buf, (iter + 2) * 16,
                            a_hi, a_lo, w_hi, w_lo, tid, row0, col0);
        copy_commit();           // always commit (possibly empty group)
    }

    #pragma unroll
    for (int mt = 0; mt < 4; ++mt) {
        #pragma unroll
        for (int n8 = 0; n8 < 4; ++n8) {
            int grow = row0 + mwarp * 64 + mt * 16 + (lane >> 2);
            int gcol = col0 + nwarp * 32 + n8 * 8 + 2 * (lane & 3);
            float2 v0 = make_float2(acc[mt][n8][0], acc[mt][n8][1]);
            float2 v1 = make_float2(acc[mt][n8][2], acc[mt][n8][3]);
            *(float2*)&g_gin[(size_t)grow * kNG + gcol]       = v0;
            *(float2*)&g_gin[(size_t)(grow + 8) * kNG + gcol] = v1;
        }
    }
}

// ---------------- scan step: gates = gin[t] + h(t-1)@Wh + b, fused cell ----------
// 128 blocks x 256 threads. tile = b>>2 (32 units x 4 gates), chunk = b&3 (K=256).
// 3-stage cp.async pipeline with always-commit. Wait-free cross-chunk reduction.
__device__ __forceinline__ void scan_load_stage(
    unsigned sa_base, unsigned sw_base, int stage, int kb,
    const __nv_bfloat16* a_hi, const __nv_bfloat16* a_lo,
    const __nv_bfloat16* w_hi, const __nv_bfloat16* w_lo,
    int tid, int unit0)
{
    int a_half = tid >> 7;
    int a_row  = (tid & 127) >> 1;
    int a_vec  = tid & 1;
    const __nv_bfloat16* a_src =
        (a_half ? a_lo : a_hi) + (size_t)a_row * kNH + kb + a_vec * 8;
    unsigned a_dst = sa_base +
        (unsigned)((((stage * 2 + a_half) * 64 + a_row) * kAStride + a_vec * 8) * 2);
    copy_async16(a_dst, a_src);

    #pragma unroll
    for (int j = 0; j < 2; ++j) {
        int id   = tid + j * 256;
        int half = id >> 8;
        int rem  = id & 255;
        int krow = rem >> 4;
        int seg  = rem & 15;
        int gate = seg >> 2;
        int vec  = seg & 3;
        const __nv_bfloat16* src = (half ? w_lo : w_hi)
            + (size_t)(kb + krow) * kNG + gate * kNH + unit0 + vec * 8;
        unsigned dst = sw_base +
            (unsigned)((((stage * 2 + half) * 16 + krow) * kWStride + gate * 32 + vec * 8) * 2);
        copy_async16(dst, src);
    }
}

__global__ __launch_bounds__(256, 1) void scan_k(
    const float* __restrict__ bias_all,
    float* __restrict__ out_buf,
    int layer, int tstep)
{
    __shared__ alignas(128) __nv_bfloat16 smem_a[3 * 2 * 64 * kAStride];
    __shared__ alignas(128) __nv_bfloat16 smem_w[3 * 2 * 16 * kWStride];
    __shared__ int smem_flag;

    const int tid   = threadIdx.x;
    const int lane  = tid & 31;
    const int warp  = tid >> 5;
    const int ncol0 = warp * 16;
    const int tile  = blockIdx.x >> 2;
    const int chunk = blockIdx.x & 3;
    const int unit0 = tile * 32;
    const int lrow  = lane & 15;
    const int lcol  = lane >> 4;
    const int kbase = chunk * 256;

    const __nv_bfloat16* a_hi = g_hist_hi + (size_t)tstep * kNB * kNH; // h(t-1)
    const __nv_bfloat16* a_lo = g_hist_lo + (size_t)tstep * kNB * kNH;
    const __nv_bfloat16* w_hi = g_Wh_hi + (size_t)layer * kNH * kNG;
    const __nv_bfloat16* w_lo = g_Wh_lo + (size_t)layer * kNH * kNG;

    const unsigned sa_base = smem_addr_u32(smem_a);
    const unsigned sw_base = smem_addr_u32(smem_w);

    float acc[4][2][4];
    #pragma unroll
    for (int mt = 0; mt < 4; ++mt)
        #pragma unroll
        for (int nt = 0; nt < 2; ++nt)
            #pragma unroll
            for (int r = 0; r < 4; ++r) acc[mt][nt][r] = 0.0f;

    scan_load_stage(sa_base, sw_base, 0, kbase,      a_hi, a_lo, w_hi, w_lo, tid, unit0);
    copy_commit();
    scan_load_stage(sa_base, sw_base, 1, kbase + 16, a_hi, a_lo, w_hi, w_lo, tid, unit0);
    copy_commit();
    scan_load_stage(sa_base, sw_base, 2, kbase + 32, a_hi, a_lo, w_hi, w_lo, tid, unit0);
    copy_commit();

    #pragma unroll 1
    for (int iter = 0; iter < 16; ++iter) {
        copy_wait2();            // 3 groups always outstanding -> oldest done
        __syncthreads();

        const int buf = iter % 3;
        unsigned a_hi_b = sa_base + (unsigned)((((buf * 2 + 0) * 64 + lrow) * kAStride + lcol * 8) * 2);
        unsigned a_lo_b = sa_base + (unsigned)((((buf * 2 + 1) * 64 + lrow) * kAStride + lcol * 8) * 2);
        unsigned w_hi_b = sw_base + (unsigned)((((buf * 2 + 0) * 16 + lrow) * kWStride + ncol0 + lcol * 8) * 2);
        unsigned w_lo_b = sw_base + (unsigned)((((buf * 2 + 1) * 16 + lrow) * kWStride + ncol0 + lcol * 8) * 2);

        unsigned fa_hi[4][4], fa_lo[4][4], fb_hi[4], fb_lo[4];
        #pragma unroll
        for (int mt = 0; mt < 4; ++mt) {
            ldmatrix_a(fa_hi[mt], a_hi_b + mt * 16 * kAStride * 2);
            ldmatrix_a(fa_lo[mt], a_lo_b + mt * 16 * kAStride * 2);
        }
        ldmatrix_bt(fb_hi, w_hi_b);
        ldmatrix_bt(fb_lo, w_lo_b);

        #pragma unroll
        for (int mt = 0; mt < 4; ++mt) {
            #pragma unroll
            for (int nt = 0; nt < 2; ++nt) {
                mma_bf16(acc[mt][nt], fa_lo[mt], &fb_hi[nt * 2]);
                mma_bf16(acc[mt][nt], fa_hi[mt], &fb_lo[nt * 2]);
                mma_bf16(acc[mt][nt], fa_hi[mt], &fb_hi[nt * 2]);
            }
        }
        __syncthreads();
        if (iter + 3 < 16)
            scan_load_stage(sa_base, sw_base, buf, kbase + (iter + 3) * 16,
                            a_hi, a_lo, w_hi, w_lo, tid, unit0);
        copy_commit();           // always commit
    }

    // ---- store partials ----
    {
        float* part = &g_part[chunk][0][0];
        #pragma unroll
        for (int mt = 0; mt < 4; ++mt) {
            #pragma unroll
            for (int nt = 0; nt < 2; ++nt) {
                int row  = mt * 16 + (lane >> 2);
                int col  = ncol0 + nt * 8 + 2 * (lane & 3);
                int gate = col >> 5;
                int gcol = gate * kNH + unit0 + (col & 31);
                float2 v0 = make_float2(acc[mt][nt][0], acc[mt][nt][1]);
                float2 v1 = make_float2(acc[mt][nt][2], acc[mt][nt][3]);
                *(float2*)&part[(size_t)row * kNG + gcol]       = v0;
                *(float2*)&part[(size_t)(row + 8) * kNG + gcol] = v1;
            }
        }
    }

    __threadfence();
    __syncthreads();
    if (tid == 0) smem_flag = atomicAdd(&g_arrive[layer * kNT + tstep][tile], 1);
    __syncthreads();

    if (smem_flag != 3) return;

    // 4th arriver: fused LSTM cell for this tile.
    __threadfence();
    const float* bias_l = bias_all + (size_t)layer * kNG;
    const float* gin_t  = g_gin + (size_t)tstep * kNB * kNG;
    __nv_bfloat16* hist_hi_n = g_hist_hi + (size_t)(tstep + 1) * kNB * kNH;
    __nv_bfloat16* hist_lo_n = g_hist_lo + (size_t)(tstep + 1) * kNB * kNH;

    #pragma unroll 1
    for (int rep = 0; rep < 8; ++rep) {
        int idx  = rep * 256 + tid;
        int uoff = idx & 31;
        int brow = idx >> 5;
        int unit = unit0 + uoff;
        float gate_i = 0.0f, gate_f = 0.0f, gate_g = 0.0f, gate_o = 0.0f;
        #pragma unroll
        for (int ch = 0; ch < 4; ++ch) {
            const float* pp = &g_part[ch][brow][0];
            gate_i += __ldcg(&pp[unit]);
            gate_f += __ldcg(&pp[kNH + unit]);
            gate_g += __ldcg(&pp[2 * kNH + unit]);
            gate_o += __ldcg(&pp[3 * kNH + unit]);
        }
        const float* gr = &gin_t[(size_t)brow * kNG];
        gate_i += gr[unit]           + bias_l[unit];
        gate_f += gr[kNH + unit]     + bias_l[kNH + unit];
        gate_g += gr[2 * kNH + unit] + bias_l[2 * kNH + unit];
        gate_o += gr[3 * kNH + unit] + bias_l[3 * kNH + unit];
        float cell_old = (tstep == 0) ? 0.0f : g_cell[brow][unit];
        float act_i = sigmoid_f(gate_i);
        float act_f = sigmoid_f(gate_f);
        float act_o = sigmoid_f(gate_o);
        float cell_new = act_f * cell_old + act_i * tanhf(gate_g);
        float hid_new  = act_o * tanhf(cell_new);
        g_cell[brow][unit] = cell_new;
        __nv_bfloat16 hid_top = __float2bfloat16_rn(hid_new);
        hist_hi_n[(size_t)brow * kNH + unit] = hid_top;
        hist_lo_n[(size_t)brow * kNH + unit] =
            __float2bfloat16_rn(hid_new - __bfloat162float(hid_top));
        if (layer == kNL - 1 && tstep == kNT - 1) {
            out_buf[(size_t)brow * kNH + unit]                         = hid_new;
            out_buf[(size_t)kNB * kNH + (size_t)brow * kNH + unit]     = hid_new;
            out_buf[(size_t)2 * kNB * kNH + (size_t)brow * kNH + unit] = cell_new;
        }
    }
}

extern "C" void kernel_launch(void* const* d_in, const int* in_sizes, int n_in,
                              void* d_out, int out_size) {
    const float* inp  = (const float*)d_in[0];  // [128,64,1024]
    const float* Wi   = (const float*)d_in[1];  // [4,1024,4096]
    const float* Wh   = (const float*)d_in[2];  // [4,1024,4096]
    const float* bias = (const float*)d_in[3];  // [4,4096]
    float* out = (float*)d_out;                 // [3,64,1024]

    prep_k<<<1024, 256>>>(Wi, Wh, inp);
    for (int l = 0; l < kNL; ++l) {
        gemm_in_k<<<dim3(32, 64), 256>>>(l);
        for (int t = 0; t < kNT; ++t) {
            scan_k<<<128, 256>>>(bias, out, l, t);
        }
    }
}